// round 5
// baseline (speedup 1.0000x reference)
#include <cuda_runtime.h>
#include <math.h>

// BATCH=128, SEQ_LEN=4096, HIDDEN=512, WINDOW=7 (W2=49), GRID=256
#define HIDDEN   512
#define WINDOW   7
#define W2       (WINDOW * WINDOW)
#define NTHREADS 1024
#define NWARPS   (NTHREADS / 32)    // 32
#define NSLOTS   16                 // smem reduction slots (pairwise-folded)
#define MAXW     2                  // ceil(49/32)

__global__ __launch_bounds__(NTHREADS, 1)
void hilbert_attn_kernel(const float* __restrict__ q,      // (B,1,H)
                         const float* __restrict__ k,      // (B,S,H)
                         const float* __restrict__ v,      // (B,S,H)
                         const int*   __restrict__ qpos,   // (B,)
                         const float* __restrict__ dscale, // ()
                         const float* __restrict__ lbias,  // (W2,)
                         const int*   __restrict__ hcoords,// (MAX_SEQ,2)
                         const int*   __restrict__ hinv,   // (GRID,GRID)
                         float*       __restrict__ out,    // (B,H)
                         int S, int grid_n)
{
    const int b    = blockIdx.x;
    const int tid  = threadIdx.x;
    const int wid  = tid >> 5;
    const int lane = tid & 31;

    __shared__ float4   s_part[NSLOTS * HIDDEN / 4];   // 32 KB, 16B aligned
    __shared__ float    s_lbias[W2];
    __shared__ int      s_pos[W2];
    __shared__ unsigned s_mask[2];
    __shared__ int      s_q2d[2];
    __shared__ float    s_scale;
    __shared__ float    s_esum[NSLOTS];

    // ---- q into registers: thread covers dims c*128 + lane*4 .. +3 ----
    float4 qv[4];
    {
        const float4* qg = reinterpret_cast<const float4*>(q + (size_t)b * HIDDEN);
        #pragma unroll
        for (int c = 0; c < 4; ++c) qv[c] = qg[c * 32 + lane];
    }

    if (tid == 0) {
        int p = qpos[b];
        s_q2d[0] = hcoords[2 * p];
        s_q2d[1] = hcoords[2 * p + 1];
        s_scale  = dscale[0];
    }
    if (tid < W2) s_lbias[tid] = lbias[tid];
    if (tid < 2)  s_mask[tid]  = 0u;
    __syncthreads();

    // ---- neighbor positions (parallel) + validity bitmask ----
    if (tid < W2) {
        int dx = tid / WINDOW - (WINDOW / 2);
        int dy = tid % WINDOW - (WINDOW / 2);
        int nx = s_q2d[0] + dx;
        int ny = s_q2d[1] + dy;
        bool ing = (nx >= 0) & (nx < grid_n) & (ny >= 0) & (ny < grid_n);
        int pos = ing ? hinv[nx * grid_n + ny] : -1;
        bool valid = ing && (pos >= 0) && (pos < S);
        s_pos[tid] = valid ? pos : -1;
        if (valid) atomicOr(&s_mask[tid >> 5], 1u << (tid & 31));
    }
    __syncthreads();

    // ---- per-warp window set: w = wid + 32*j, j = 0..1 ----
    const unsigned m0 = s_mask[0], m1 = s_mask[1];
    const float scale = s_scale;

    int   mypos[MAXW];
    float myval[MAXW];
    float mylw[MAXW];

    #pragma unroll
    for (int j = 0; j < MAXW; ++j) {
        int w = wid + NWARPS * j;
        int p = (w < W2) ? s_pos[w] : -1;
        bool valid = (p >= 0);
        mypos[j] = valid ? p : 0;
        myval[j] = valid ? 1.0f : 0.0f;
        float lw = 0.0f;
        if (valid) {
            int c;
            if (w < 32) {
                unsigned mm = (w == 31) ? 0xffffffffu : ((2u << w) - 1u);
                c = __popc(m0 & mm) - 1;
            } else {
                unsigned mm = (2u << (w - 32)) - 1u;
                c = __popc(m0) + __popc(m1 & mm) - 1;
            }
            int dx = w / WINDOW - (WINDOW / 2);
            int dy = w % WINDOW - (WINDOW / 2);
            float dist = (float)(abs(dx) + abs(dy));
            lw = logf(__expf(-dist * scale) + s_lbias[c] + 1e-8f);
        }
        mylw[j] = lw;
    }

    const float* kb = k + (size_t)b * S * HIDDEN;
    const float* vb = v + (size_t)b * S * HIDDEN;
    const float4* kr[MAXW];
    const float4* vr[MAXW];
    #pragma unroll
    for (int j = 0; j < MAXW; ++j) {
        kr[j] = reinterpret_cast<const float4*>(kb + (size_t)mypos[j] * HIDDEN);
        vr[j] = reinterpret_cast<const float4*>(vb + (size_t)mypos[j] * HIDDEN);
    }

    // ---- dots: chunk-major, unconditional loads ----
    float d[MAXW] = {0.f, 0.f};
    #pragma unroll
    for (int c = 0; c < 4; ++c) {
        float4 kk[MAXW];
        #pragma unroll
        for (int j = 0; j < MAXW; ++j) kk[j] = kr[j][c * 32 + lane];
        #pragma unroll
        for (int j = 0; j < MAXW; ++j)
            d[j] += kk[j].x * qv[c].x + kk[j].y * qv[c].y
                  + kk[j].z * qv[c].z + kk[j].w * qv[c].w;
    }

    #pragma unroll
    for (int off = 16; off > 0; off >>= 1) {
        #pragma unroll
        for (int j = 0; j < MAXW; ++j)
            d[j] += __shfl_xor_sync(0xffffffffu, d[j], off);
    }

    // ---- unnormalized exp weights (0 for invalid windows) ----
    const float inv_sqrt_h = 0.04419417382415922f; // 1/sqrt(512)
    float e[MAXW];
    float esum = 0.0f;
    #pragma unroll
    for (int j = 0; j < MAXW; ++j) {
        e[j] = myval[j] * __expf(d[j] * inv_sqrt_h + mylw[j]);
        esum += e[j];
    }

    // ---- weighted V accumulation ----
    float4 acc[4];
    #pragma unroll
    for (int c = 0; c < 4; ++c) acc[c] = make_float4(0.f, 0.f, 0.f, 0.f);
    #pragma unroll
    for (int c = 0; c < 4; ++c) {
        float4 vv[MAXW];
        #pragma unroll
        for (int j = 0; j < MAXW; ++j) vv[j] = vr[j][c * 32 + lane];
        #pragma unroll
        for (int j = 0; j < MAXW; ++j) {
            acc[c].x += e[j] * vv[j].x;
            acc[c].y += e[j] * vv[j].y;
            acc[c].z += e[j] * vv[j].z;
            acc[c].w += e[j] * vv[j].w;
        }
    }

    // ---- cross-warp reduction, pairwise folded into 16 slots ----
    // Stage A: warps 0..15 write their partials.
    if (wid < NSLOTS) {
        float4* sp = &s_part[wid * (HIDDEN / 4)];
        #pragma unroll
        for (int c = 0; c < 4; ++c) sp[c * 32 + lane] = acc[c];
        if (lane == 0) s_esum[wid] = esum;
    }
    __syncthreads();
    // Stage B: warps 16..31 add into slot (wid-16). Single writer per word.
    if (wid >= NSLOTS) {
        float4* sp = &s_part[(wid - NSLOTS) * (HIDDEN / 4)];
        #pragma unroll
        for (int c = 0; c < 4; ++c) {
            float4 t = sp[c * 32 + lane];
            t.x += acc[c].x; t.y += acc[c].y; t.z += acc[c].z; t.w += acc[c].w;
            sp[c * 32 + lane] = t;
        }
        if (lane == 0) s_esum[wid - NSLOTS] += esum;
    }
    __syncthreads();

    // ---- final 16-slot sum + normalize (threads 0..511) ----
    if (tid < HIDDEN) {
        const float* s_part_f = reinterpret_cast<const float*>(s_part);
        float num = 0.0f;
        #pragma unroll
        for (int s = 0; s < NSLOTS; ++s) num += s_part_f[s * HIDDEN + tid];
        float den = 0.0f;
        #pragma unroll
        for (int s = 0; s < NSLOTS; ++s) den += s_esum[s];
        out[(size_t)b * HIDDEN + tid] = num / den;
    }
}

extern "C" void kernel_launch(void* const* d_in, const int* in_sizes, int n_in,
                              void* d_out, int out_size)
{
    const float* q       = (const float*)d_in[0];
    const float* k       = (const float*)d_in[1];
    const float* v       = (const float*)d_in[2];
    const int*   qpos    = (const int*)d_in[3];
    const float* dscale  = (const float*)d_in[4];
    const float* lbias   = (const float*)d_in[5];
    const int*   hcoords = (const int*)d_in[6];
    const int*   hinv    = (const int*)d_in[7];
    float*       out     = (float*)d_out;

    int B = in_sizes[3];                      // 128
    int H = in_sizes[0] / B;                  // 512
    int S = in_sizes[1] / (B * H);            // 4096
    int inv_elems = in_sizes[7];              // grid*grid
    int grid_n = 1;
    while (grid_n * grid_n < inv_elems) grid_n <<= 1;  // 256

    hilbert_attn_kernel<<<B, NTHREADS>>>(q, k, v, qpos, dscale, lbias,
                                         hcoords, hinv, out, S, grid_n);
}

// round 6
// speedup vs baseline: 1.0294x; 1.0294x over previous
#include <cuda_runtime.h>
#include <math.h>

// BATCH=128, SEQ_LEN=4096, HIDDEN=512, WINDOW=7 (W2=49), GRID=256
#define HIDDEN   512
#define WINDOW   7
#define W2       (WINDOW * WINDOW)
#define NTHREADS 1024
#define NWARPS   (NTHREADS / 32)    // 32
#define NSLOTS   16                 // smem reduction slots (pairwise-folded)
#define MAXW     2                  // ceil(49/32)

__global__ __launch_bounds__(NTHREADS, 1)
void hilbert_attn_kernel(const float* __restrict__ q,      // (B,1,H)
                         const float* __restrict__ k,      // (B,S,H)
                         const float* __restrict__ v,      // (B,S,H)
                         const int*   __restrict__ qpos,   // (B,)
                         const float* __restrict__ dscale, // ()
                         const float* __restrict__ lbias,  // (W2,)
                         const int*   __restrict__ hcoords,// (MAX_SEQ,2)
                         const int*   __restrict__ hinv,   // (GRID,GRID)
                         float*       __restrict__ out,    // (B,H)
                         int S, int grid_n)
{
    const int b    = blockIdx.x;
    const int tid  = threadIdx.x;
    const int wid  = tid >> 5;
    const int lane = tid & 31;
    const unsigned FULL = 0xffffffffu;

    __shared__ float4 s_part[NSLOTS * HIDDEN / 4];   // 32 KB, 16B aligned
    __shared__ float  s_esum[NSLOTS];

    // ---- q slice into registers (independent, issues immediately) ----
    float4 qv[4];
    {
        const float4* qg = reinterpret_cast<const float4*>(q + (size_t)b * HIDDEN);
        #pragma unroll
        for (int c = 0; c < 4; ++c) qv[c] = qg[c * 32 + lane];
    }

    // ---- warp-autonomous window resolution (NO block barriers) ----
    // Every warp redundantly resolves all 49 windows:
    //   round A: lane l -> window l        (l in [0,32))
    //   round B: lane l -> window l + 32   (l in [0,17))
    const int p   = qpos[b];                 // warp-broadcast loads
    const int qx  = hcoords[2 * p];
    const int qy  = hcoords[2 * p + 1];
    const float scale = dscale[0];

    int wA = lane;
    int dxA = wA / WINDOW - (WINDOW / 2);
    int dyA = wA % WINDOW - (WINDOW / 2);
    int nxA = qx + dxA, nyA = qy + dyA;
    bool ingA = (nxA >= 0) & (nxA < grid_n) & (nyA >= 0) & (nyA < grid_n);
    int posA = ingA ? hinv[nxA * grid_n + nyA] : -1;
    bool vA = ingA && (posA >= 0) && (posA < S);

    int wB = lane + 32;
    bool inB = (wB < W2);
    int dxB = inB ? (wB / WINDOW - (WINDOW / 2)) : 0;
    int dyB = inB ? (wB % WINDOW - (WINDOW / 2)) : 0;
    int nxB = qx + dxB, nyB = qy + dyB;
    bool ingB = inB & (nxB >= 0) & (nxB < grid_n) & (nyB >= 0) & (nyB < grid_n);
    int posB = ingB ? hinv[nxB * grid_n + nyB] : -1;
    bool vB = ingB && (posB >= 0) && (posB < S);

    const unsigned m0 = __ballot_sync(FULL, vA);
    const unsigned m1 = __ballot_sync(FULL, vB);

    // This warp's two windows: w = wid and w = wid + 32 (wid < 17)
    int   mypos[MAXW];
    float myval[MAXW];
    float mylw[MAXW];
    {
        // window wid (from round A, lane `wid`)
        int p0 = __shfl_sync(FULL, posA, wid);
        bool ok0 = (m0 >> wid) & 1u;
        mypos[0] = ok0 ? p0 : 0;
        myval[0] = ok0 ? 1.0f : 0.0f;
        float lw0 = 0.0f;
        if (ok0) {
            int c = __popc(m0 & ((2u << wid) - 1u)) - 1;  // wid=31: mask=0xffffffff
            int dist = abs(wid / WINDOW - 3) + abs(wid % WINDOW - 3);
            lw0 = __logf(__expf(-(float)dist * scale) + __ldg(lbias + c) + 1e-8f);
        }
        mylw[0] = lw0;

        // window wid+32 (from round B, lane `wid`), only wid < 17
        int p1 = __shfl_sync(FULL, posB, wid);
        bool ok1 = (wid < W2 - 32) && ((m1 >> wid) & 1u);
        mypos[1] = ok1 ? p1 : 0;
        myval[1] = ok1 ? 1.0f : 0.0f;
        float lw1 = 0.0f;
        if (ok1) {
            int w = wid + 32;
            int c = __popc(m0) + __popc(m1 & ((2u << wid) - 1u)) - 1;
            int dist = abs(w / WINDOW - 3) + abs(w % WINDOW - 3);
            lw1 = __logf(__expf(-(float)dist * scale) + __ldg(lbias + c) + 1e-8f);
        }
        mylw[1] = lw1;
    }

    const float* kb = k + (size_t)b * S * HIDDEN;
    const float* vb = v + (size_t)b * S * HIDDEN;
    const float4* kr[MAXW];
    const float4* vr[MAXW];
    #pragma unroll
    for (int j = 0; j < MAXW; ++j) {
        kr[j] = reinterpret_cast<const float4*>(kb + (size_t)mypos[j] * HIDDEN);
        vr[j] = reinterpret_cast<const float4*>(vb + (size_t)mypos[j] * HIDDEN);
    }

    // ---- dots: chunk-major, unconditional loads ----
    float d[MAXW] = {0.f, 0.f};
    #pragma unroll
    for (int c = 0; c < 4; ++c) {
        float4 kk[MAXW];
        #pragma unroll
        for (int j = 0; j < MAXW; ++j) kk[j] = kr[j][c * 32 + lane];
        #pragma unroll
        for (int j = 0; j < MAXW; ++j)
            d[j] += kk[j].x * qv[c].x + kk[j].y * qv[c].y
                  + kk[j].z * qv[c].z + kk[j].w * qv[c].w;
    }

    #pragma unroll
    for (int off = 16; off > 0; off >>= 1) {
        #pragma unroll
        for (int j = 0; j < MAXW; ++j)
            d[j] += __shfl_xor_sync(FULL, d[j], off);
    }

    // ---- unnormalized exp weights (0 for invalid windows) ----
    const float inv_sqrt_h = 0.04419417382415922f; // 1/sqrt(512)
    float e[MAXW];
    float esum = 0.0f;
    #pragma unroll
    for (int j = 0; j < MAXW; ++j) {
        e[j] = myval[j] * __expf(d[j] * inv_sqrt_h + mylw[j]);
        esum += e[j];
    }

    // ---- weighted V accumulation ----
    float4 acc[4];
    #pragma unroll
    for (int c = 0; c < 4; ++c) acc[c] = make_float4(0.f, 0.f, 0.f, 0.f);
    #pragma unroll
    for (int c = 0; c < 4; ++c) {
        float4 vv[MAXW];
        #pragma unroll
        for (int j = 0; j < MAXW; ++j) vv[j] = vr[j][c * 32 + lane];
        #pragma unroll
        for (int j = 0; j < MAXW; ++j) {
            acc[c].x += e[j] * vv[j].x;
            acc[c].y += e[j] * vv[j].y;
            acc[c].z += e[j] * vv[j].z;
            acc[c].w += e[j] * vv[j].w;
        }
    }

    // ---- cross-warp reduction, pairwise folded into 16 slots ----
    if (wid < NSLOTS) {
        float4* sp = &s_part[wid * (HIDDEN / 4)];
        #pragma unroll
        for (int c = 0; c < 4; ++c) sp[c * 32 + lane] = acc[c];
        if (lane == 0) s_esum[wid] = esum;
    }
    __syncthreads();
    if (wid >= NSLOTS) {
        float4* sp = &s_part[(wid - NSLOTS) * (HIDDEN / 4)];
        #pragma unroll
        for (int c = 0; c < 4; ++c) {
            float4 t = sp[c * 32 + lane];
            t.x += acc[c].x; t.y += acc[c].y; t.z += acc[c].z; t.w += acc[c].w;
            sp[c * 32 + lane] = t;
        }
        if (lane == 0) s_esum[wid - NSLOTS] += esum;
    }
    __syncthreads();

    // ---- final 16-slot sum + normalize (threads 0..511) ----
    if (tid < HIDDEN) {
        const float* s_part_f = reinterpret_cast<const float*>(s_part);
        float num = 0.0f;
        #pragma unroll
        for (int s = 0; s < NSLOTS; ++s) num += s_part_f[s * HIDDEN + tid];
        float den = 0.0f;
        #pragma unroll
        for (int s = 0; s < NSLOTS; ++s) den += s_esum[s];
        out[(size_t)b * HIDDEN + tid] = num / den;
    }
}

extern "C" void kernel_launch(void* const* d_in, const int* in_sizes, int n_in,
                              void* d_out, int out_size)
{
    const float* q       = (const float*)d_in[0];
    const float* k       = (const float*)d_in[1];
    const float* v       = (const float*)d_in[2];
    const int*   qpos    = (const int*)d_in[3];
    const float* dscale  = (const float*)d_in[4];
    const float* lbias   = (const float*)d_in[5];
    const int*   hcoords = (const int*)d_in[6];
    const int*   hinv    = (const int*)d_in[7];
    float*       out     = (float*)d_out;

    int B = in_sizes[3];                      // 128
    int H = in_sizes[0] / B;                  // 512
    int S = in_sizes[1] / (B * H);            // 4096
    int inv_elems = in_sizes[7];              // grid*grid
    int grid_n = 1;
    while (grid_n * grid_n < inv_elems) grid_n <<= 1;  // 256

    hilbert_attn_kernel<<<B, NTHREADS>>>(q, k, v, qpos, dscale, lbias,
                                         hcoords, hinv, out, S, grid_n);
}